// round 12
// baseline (speedup 1.0000x reference)
#include <cuda_runtime.h>

#define NE      262144      // edges
#define NMAT_SH 13          // log2(8192)
#define EPSV    1e-8f

#define NBLOCKS  256
#define NTHREADS 64
#define EPT      16                      // edges per thread: 16 pos + 16 neg gathers
#define EPB      (NTHREADS * EPT)        // 1024 edges per block; NBLOCKS*EPB == NE

#define FXSCALE 16777216.0               // 2^24 fixed-point scale

// Deterministic integer accumulator + completion ticket (device globals).
__device__ unsigned long long g_acc;     // zero-init; reset by last block
__device__ unsigned int       g_count;

// COHERENT gather with L2 evict-last policy (not .nc — the RO path may install
// lines in a replacement class where evict_last is ineffective).
__device__ __forceinline__ float ld_gather(const float* p, unsigned long long pol) {
    float v;
    asm volatile("ld.global.L2::cache_hint.f32 %0, [%1], %2;"
                 : "=f"(v) : "l"(p), "l"(pol));
    return v;
}

// Streaming index load with evict-first policy: 6MB/replay of one-shot data
// must not displace the resident adjacency lines.
__device__ __forceinline__ int4 ld_idx4(const int* p, unsigned long long pol) {
    int4 v;
    asm volatile("ld.global.nc.L2::cache_hint.v4.b32 {%0,%1,%2,%3}, [%4], %5;"
                 : "=r"(v.x), "=r"(v.y), "=r"(v.z), "=r"(v.w)
                 : "l"(p), "l"(pol));
    return v;
}

__global__ void __launch_bounds__(NTHREADS, 1)
fused_loss_kernel(const float* __restrict__ adj,
                  const int*   __restrict__ edge_index,   // [2, E]
                  const int*   __restrict__ neg_edges,    // [E, 2]
                  const float* __restrict__ codebook,
                  float*       __restrict__ out)
{
    const int tid = threadIdx.x;
    const int bid = blockIdx.x;
    const int e0  = bid * EPB + EPT * tid;   // this thread: edges e0..e0+15

    unsigned long long polL, polF;
    asm volatile("createpolicy.fractional.L2::evict_last.b64 %0, 1.0;"  : "=l"(polL));
    asm volatile("createpolicy.fractional.L2::evict_first.b64 %0, 1.0;" : "=l"(polF));

    // ---- Phase 1: coalesced vector index loads (evict_first) — all named scalars ----
    const int4 sA = ld_idx4(&edge_index[e0],            polF);
    const int4 sB = ld_idx4(&edge_index[e0 + 4],        polF);
    const int4 sC = ld_idx4(&edge_index[e0 + 8],        polF);
    const int4 sD = ld_idx4(&edge_index[e0 + 12],       polF);
    const int4 dA = ld_idx4(&edge_index[NE + e0],       polF);
    const int4 dB = ld_idx4(&edge_index[NE + e0 + 4],   polF);
    const int4 dC = ld_idx4(&edge_index[NE + e0 + 8],   polF);
    const int4 dD = ld_idx4(&edge_index[NE + e0 + 12],  polF);
    const int4 n0 = ld_idx4(&neg_edges[2 * e0],         polF);
    const int4 n1 = ld_idx4(&neg_edges[2 * e0 + 4],     polF);
    const int4 n2 = ld_idx4(&neg_edges[2 * e0 + 8],     polF);
    const int4 n3 = ld_idx4(&neg_edges[2 * e0 + 12],    polF);
    const int4 n4 = ld_idx4(&neg_edges[2 * e0 + 16],    polF);
    const int4 n5 = ld_idx4(&neg_edges[2 * e0 + 20],    polF);
    const int4 n6 = ld_idx4(&neg_edges[2 * e0 + 24],    polF);
    const int4 n7 = ld_idx4(&neg_edges[2 * e0 + 28],    polF);

    // ---- Phase 2: all 32 gathers issued back-to-back (evict_last, coherent) ----
    const float p0  = ld_gather(&adj[(sA.x << NMAT_SH) + dA.x], polL);
    const float p1  = ld_gather(&adj[(sA.y << NMAT_SH) + dA.y], polL);
    const float p2  = ld_gather(&adj[(sA.z << NMAT_SH) + dA.z], polL);
    const float p3  = ld_gather(&adj[(sA.w << NMAT_SH) + dA.w], polL);
    const float p4  = ld_gather(&adj[(sB.x << NMAT_SH) + dB.x], polL);
    const float p5  = ld_gather(&adj[(sB.y << NMAT_SH) + dB.y], polL);
    const float p6  = ld_gather(&adj[(sB.z << NMAT_SH) + dB.z], polL);
    const float p7  = ld_gather(&adj[(sB.w << NMAT_SH) + dB.w], polL);
    const float p8  = ld_gather(&adj[(sC.x << NMAT_SH) + dC.x], polL);
    const float p9  = ld_gather(&adj[(sC.y << NMAT_SH) + dC.y], polL);
    const float p10 = ld_gather(&adj[(sC.z << NMAT_SH) + dC.z], polL);
    const float p11 = ld_gather(&adj[(sC.w << NMAT_SH) + dC.w], polL);
    const float p12 = ld_gather(&adj[(sD.x << NMAT_SH) + dD.x], polL);
    const float p13 = ld_gather(&adj[(sD.y << NMAT_SH) + dD.y], polL);
    const float p14 = ld_gather(&adj[(sD.z << NMAT_SH) + dD.z], polL);
    const float p15 = ld_gather(&adj[(sD.w << NMAT_SH) + dD.w], polL);
    const float q0  = ld_gather(&adj[(n0.x << NMAT_SH) + n0.y], polL);
    const float q1  = ld_gather(&adj[(n0.z << NMAT_SH) + n0.w], polL);
    const float q2  = ld_gather(&adj[(n1.x << NMAT_SH) + n1.y], polL);
    const float q3  = ld_gather(&adj[(n1.z << NMAT_SH) + n1.w], polL);
    const float q4  = ld_gather(&adj[(n2.x << NMAT_SH) + n2.y], polL);
    const float q5  = ld_gather(&adj[(n2.z << NMAT_SH) + n2.w], polL);
    const float q6  = ld_gather(&adj[(n3.x << NMAT_SH) + n3.y], polL);
    const float q7  = ld_gather(&adj[(n3.z << NMAT_SH) + n3.w], polL);
    const float q8  = ld_gather(&adj[(n4.x << NMAT_SH) + n4.y], polL);
    const float q9  = ld_gather(&adj[(n4.z << NMAT_SH) + n4.w], polL);
    const float q10 = ld_gather(&adj[(n5.x << NMAT_SH) + n5.y], polL);
    const float q11 = ld_gather(&adj[(n5.z << NMAT_SH) + n5.w], polL);
    const float q12 = ld_gather(&adj[(n6.x << NMAT_SH) + n6.y], polL);
    const float q13 = ld_gather(&adj[(n6.z << NMAT_SH) + n6.w], polL);
    const float q14 = ld_gather(&adj[(n7.x << NMAT_SH) + n7.y], polL);
    const float q15 = ld_gather(&adj[(n7.z << NMAT_SH) + n7.w], polL);

    // ---- Phase 3: fold 32 terms into EIGHT logs (each 4-term product in [1e-32,1]) ----
    float pr0 = ((p0  + EPSV) * (p1  + EPSV)) * ((p2  + EPSV) * (p3  + EPSV));
    float pr1 = ((p4  + EPSV) * (p5  + EPSV)) * ((p6  + EPSV) * (p7  + EPSV));
    float pr2 = ((p8  + EPSV) * (p9  + EPSV)) * ((p10 + EPSV) * (p11 + EPSV));
    float pr3 = ((p12 + EPSV) * (p13 + EPSV)) * ((p14 + EPSV) * (p15 + EPSV));
    float qr0 = ((1.0f - q0  + EPSV) * (1.0f - q1  + EPSV)) * ((1.0f - q2  + EPSV) * (1.0f - q3  + EPSV));
    float qr1 = ((1.0f - q4  + EPSV) * (1.0f - q5  + EPSV)) * ((1.0f - q6  + EPSV) * (1.0f - q7  + EPSV));
    float qr2 = ((1.0f - q8  + EPSV) * (1.0f - q9  + EPSV)) * ((1.0f - q10 + EPSV) * (1.0f - q11 + EPSV));
    float qr3 = ((1.0f - q12 + EPSV) * (1.0f - q13 + EPSV)) * ((1.0f - q14 + EPSV) * (1.0f - q15 + EPSV));
    float acc = ((__logf(pr0) + __logf(pr1)) + (__logf(pr2) + __logf(pr3)))
              + ((__logf(qr0) + __logf(qr1)) + (__logf(qr2) + __logf(qr3)));

    // ---- Phase 4: warp + block reduction (2 warps) ----
#pragma unroll
    for (int off = 16; off > 0; off >>= 1)
        acc += __shfl_down_sync(0xFFFFFFFFu, acc, off);

    __shared__ float s_acc[NTHREADS / 32];
    const int lane = tid & 31;
    const int wid  = tid >> 5;
    if (lane == 0) s_acc[wid] = acc;
    __syncthreads();

    if (tid == 0) {
        double dsum = 0.0;
#pragma unroll
        for (int w = 0; w < NTHREADS / 32; w++) dsum += (double)s_acc[w];

        // Exact, order-independent integer accumulation (deterministic).
        atomicAdd(&g_acc, (unsigned long long)llrint(dsum * FXSCALE));
        __threadfence();
        unsigned int ticket = atomicAdd(&g_count, 1u);

        // ---- Phase 5: last block finalizes (tiny tail) ----
        if (ticket == NBLOCKS - 1) {
            unsigned long long u = atomicAdd(&g_acc, 0ULL);   // strong read
            double total = (double)(long long)u / FXSCALE;
            double loss  = -total / (double)NE
                         + (double)codebook[0] + (double)codebook[1]
                         + (double)codebook[2] + (double)codebook[3];
            out[0] = (float)loss;
            // Reset scratch for next graph replay (stream-ordered).
            g_acc = 0ULL;
            __threadfence();
            g_count = 0;
        }
    }
}

extern "C" void kernel_launch(void* const* d_in, const int* in_sizes, int n_in,
                              void* d_out, int out_size)
{
    const float* adj        = (const float*)d_in[0];   // [N*N] fp32
    const float* codebook   = (const float*)d_in[1];   // [6] fp32
    const int*   edge_index = (const int*)d_in[2];     // [2*E] int32
    const int*   neg_edges  = (const int*)d_in[3];     // [E*2] int32
    float* out = (float*)d_out;

    fused_loss_kernel<<<NBLOCKS, NTHREADS>>>(adj, edge_index, neg_edges, codebook, out);
}

// round 13
// speedup vs baseline: 1.0025x; 1.0025x over previous
#include <cuda_runtime.h>

#define NE      262144      // edges
#define NMAT_SH 13          // log2(8192)
#define EPSV    1e-8f

#define NBLOCKS  296        // exactly 2 CTAs per SM on 148 SMs -> uniform makespan
#define NTHREADS 64
#define EPT      14         // edges per thread; 296*64*14 = 265216 >= NE (1.2% predicated)
#define EPB      (NTHREADS * EPT)   // 896 edges per block

#define FXSCALE 16777216.0          // 2^24 fixed-point scale

// Deterministic integer accumulator + completion ticket (device globals).
__device__ unsigned long long g_acc;     // zero-init; reset by last block
__device__ unsigned int       g_count;

__global__ void __launch_bounds__(NTHREADS, 1)
fused_loss_kernel(const float* __restrict__ adj,
                  const int*   __restrict__ edge_index,   // [2, E]
                  const int*   __restrict__ neg_edges,    // [E, 2]
                  const float* __restrict__ codebook,
                  float*       __restrict__ out)
{
    const int tid  = threadIdx.x;
    const int bid  = blockIdx.x;
    const int base = bid * EPB + tid;     // edges: base + 64*k, k = 0..13 (coalesced)

    // ---- Phase 1: index loads (clamped; coalesced 64-wide) ----
    int   es[EPT];
    bool  ok[EPT];
    int   s[EPT], d[EPT];
    int2  ng[EPT];
#pragma unroll
    for (int k = 0; k < EPT; k++) {
        int e  = base + 64 * k;
        ok[k]  = (e < NE);
        es[k]  = ok[k] ? e : (NE - 1);    // safe clamp for the 1.2% tail
    }
#pragma unroll
    for (int k = 0; k < EPT; k++) s[k]  = __ldg(&edge_index[es[k]]);
#pragma unroll
    for (int k = 0; k < EPT; k++) d[k]  = __ldg(&edge_index[NE + es[k]]);
#pragma unroll
    for (int k = 0; k < EPT; k++) ng[k] = __ldg(&((const int2*)neg_edges)[es[k]]);

    // ---- Phase 2: all 28 gathers issued back-to-back (32-bit flat indices) ----
    float p[EPT], q[EPT];
#pragma unroll
    for (int k = 0; k < EPT; k++)
        p[k] = __ldg(&adj[(s[k] << NMAT_SH) + d[k]]);
#pragma unroll
    for (int k = 0; k < EPT; k++)
        q[k] = __ldg(&adj[(ng[k].x << NMAT_SH) + ng[k].y]);

    // ---- Phase 3: per-edge terms (OOB edges contribute exactly log(1)=0) ----
    float pt[EPT], qt[EPT];
#pragma unroll
    for (int k = 0; k < EPT; k++) {
        pt[k] = ok[k] ? (p[k] + EPSV)        : 1.0f;
        qt[k] = ok[k] ? (1.0f - q[k] + EPSV) : 1.0f;
    }

    // Fold 14 terms/stream into 4+4+4+2 products (each >= 1e-32, normal fp32).
    float pa = (pt[0] * pt[1]) * (pt[2]  * pt[3]);
    float pb = (pt[4] * pt[5]) * (pt[6]  * pt[7]);
    float pc = (pt[8] * pt[9]) * (pt[10] * pt[11]);
    float pd =  pt[12] * pt[13];
    float qa = (qt[0] * qt[1]) * (qt[2]  * qt[3]);
    float qb = (qt[4] * qt[5]) * (qt[6]  * qt[7]);
    float qc = (qt[8] * qt[9]) * (qt[10] * qt[11]);
    float qd =  qt[12] * qt[13];
    float acc = ((__logf(pa) + __logf(pb)) + (__logf(pc) + __logf(pd)))
              + ((__logf(qa) + __logf(qb)) + (__logf(qc) + __logf(qd)));

    // ---- Phase 4: warp + block reduction (2 warps) ----
#pragma unroll
    for (int off = 16; off > 0; off >>= 1)
        acc += __shfl_down_sync(0xFFFFFFFFu, acc, off);

    __shared__ float s_acc[NTHREADS / 32];
    const int lane = tid & 31;
    const int wid  = tid >> 5;
    if (lane == 0) s_acc[wid] = acc;
    __syncthreads();

    if (tid == 0) {
        double dsum = (double)s_acc[0] + (double)s_acc[1];

        // Exact, order-independent integer accumulation (deterministic).
        atomicAdd(&g_acc, (unsigned long long)llrint(dsum * FXSCALE));
        __threadfence();
        unsigned int ticket = atomicAdd(&g_count, 1u);

        // ---- Phase 5: last block finalizes (tiny tail) ----
        if (ticket == NBLOCKS - 1) {
            unsigned long long u = atomicAdd(&g_acc, 0ULL);   // strong read
            double total = (double)(long long)u / FXSCALE;
            double loss  = -total / (double)NE
                         + (double)codebook[0] + (double)codebook[1]
                         + (double)codebook[2] + (double)codebook[3];
            out[0] = (float)loss;
            // Reset scratch for next graph replay (stream-ordered).
            g_acc = 0ULL;
            __threadfence();
            g_count = 0;
        }
    }
}

extern "C" void kernel_launch(void* const* d_in, const int* in_sizes, int n_in,
                              void* d_out, int out_size)
{
    const float* adj        = (const float*)d_in[0];   // [N*N] fp32
    const float* codebook   = (const float*)d_in[1];   // [6] fp32
    const int*   edge_index = (const int*)d_in[2];     // [2*E] int32
    const int*   neg_edges  = (const int*)d_in[3];     // [E*2] int32
    float* out = (float*)d_out;

    fused_loss_kernel<<<NBLOCKS, NTHREADS>>>(adj, edge_index, neg_edges, codebook, out);
}